// round 1
// baseline (speedup 1.0000x reference)
#include <cuda_runtime.h>
#include <math.h>

// Problem constants
#define BB   2
#define SS   2048
#define EE   1024
#define HH   16
#define DD   64
#define MTOT (BB*SS)   // 4096

// Scratch (allocation-free rule: __device__ globals)
__device__ float g_qh[(size_t)BB*HH*SS*DD];   // [B*H][S][D]
__device__ float g_kh[(size_t)BB*HH*SS*DD];
__device__ float g_vh[(size_t)BB*HH*SS*DD];
__device__ float g_attn[(size_t)MTOT*EE];     // [B*S][E] (head outputs interleaved)

// ---------------------------------------------------------------------------
// C[M,N] = A[M,K] * W[N,K]^T   (M=4096, N=K=1024)
// mode 0: C[m*N+n] flat.  mode 1: head-major scatter qh[((b*H+h)*S+s)*D+d]
// 64x64 block tile, BK=16, 256 threads, 4x4 per thread.
// ---------------------------------------------------------------------------
__global__ void __launch_bounds__(256)
proj_kernel(const float* __restrict__ A, const float* __restrict__ W,
            float* __restrict__ C, int mode)
{
    const int K = EE, N = EE;
    __shared__ __align__(16) float As[16][68];   // A tile transposed: As[k][m]
    __shared__ __align__(16) float Bs[16][68];   // W tile transposed: Bs[k][n]

    const int tid = threadIdx.x;
    const int tx = tid & 15, ty = tid >> 4;
    const int m0 = blockIdx.y * 64, n0 = blockIdx.x * 64;
    const int lk = tid & 15;       // k within tile
    const int lr = tid >> 4;       // base row within pass

    float acc[4][4] = {};

    for (int k0 = 0; k0 < K; k0 += 16) {
        #pragma unroll
        for (int p = 0; p < 4; p++) {
            int row = lr + 16 * p;
            As[lk][row] = A[(size_t)(m0 + row) * K + k0 + lk];
            Bs[lk][row] = W[(size_t)(n0 + row) * K + k0 + lk];
        }
        __syncthreads();
        #pragma unroll
        for (int kk = 0; kk < 16; kk++) {
            float4 a = *(const float4*)&As[kk][4 * ty];
            float4 b = *(const float4*)&Bs[kk][4 * tx];
            float av[4] = {a.x, a.y, a.z, a.w};
            float bv[4] = {b.x, b.y, b.z, b.w};
            #pragma unroll
            for (int i = 0; i < 4; i++)
                #pragma unroll
                for (int j = 0; j < 4; j++)
                    acc[i][j] += av[i] * bv[j];
        }
        __syncthreads();
    }

    #pragma unroll
    for (int i = 0; i < 4; i++) {
        int m = m0 + 4 * ty + i;
        int n = n0 + 4 * tx;
        float4 v = make_float4(acc[i][0], acc[i][1], acc[i][2], acc[i][3]);
        if (mode == 0) {
            *(float4*)&C[(size_t)m * N + n] = v;
        } else {
            int b = m / SS, s = m % SS;
            int h = n / DD, d = n & (DD - 1);       // n0 is a multiple of 64 -> h constant
            *(float4*)&C[(((size_t)(b * HH + h)) * SS + s) * DD + d] = v;
        }
    }
}

// ---------------------------------------------------------------------------
// Flash attention: one block = (b,h) pair x 64 q-rows. BN=64 k-block, D=64.
// qs/ks stored d-major (transposed) for conflict-free float4 inner loops.
// mask: nonzero (as 32-bit word) = masked -> score := -1e9 (matches reference,
// robust whether the bool mask arrives as int32 or float32).
// ---------------------------------------------------------------------------
__global__ void __launch_bounds__(256)
flash_kernel(const int* __restrict__ mask)
{
    extern __shared__ __align__(16) float sm[];
    float* qs   = sm;                  // [64][68]  qs[d][m]
    float* ks   = qs + 64 * 68;        // [64][68]  ks[d][n]
    float* vs   = ks + 64 * 68;        // [64][68]  vs[n][d]
    float* ps   = vs + 64 * 68;        // [64][68]  ps[m][n]
    float* rowm = ps + 64 * 68;        // [64]
    float* rowl = rowm + 64;
    float* rowa = rowl + 64;

    const int tid = threadIdx.x;
    const int tx = tid & 15, ty = tid >> 4;
    const int bh = blockIdx.y;
    const int b  = bh / HH, h = bh % HH;
    const int q0 = blockIdx.x * 64;

    const float* qptr = g_qh + (size_t)bh * SS * DD;
    const float* kptr = g_kh + (size_t)bh * SS * DD;
    const float* vptr = g_vh + (size_t)bh * SS * DD;
    const int*   mrow = mask + (size_t)b * SS * SS;

    // load q tile transposed
    for (int idx = tid; idx < 64 * 64; idx += 256) {
        int r = idx >> 6, d = idx & 63;
        qs[d * 68 + r] = qptr[(size_t)(q0 + r) * DD + d];
    }
    if (tid < 64) { rowm[tid] = -INFINITY; rowl[tid] = 0.0f; }
    __syncthreads();

    float o[4][4] = {};

    for (int k0 = 0; k0 < SS; k0 += 64) {
        // load K (transposed) + V (natural) tiles
        for (int idx = tid; idx < 64 * 64; idx += 256) {
            int r = idx >> 6, d = idx & 63;
            ks[d * 68 + r] = kptr[(size_t)(k0 + r) * DD + d];
            vs[r * 68 + d] = vptr[(size_t)(k0 + r) * DD + d];
        }
        __syncthreads();

        // S = q @ k^T   (4x4 per thread)
        float s[4][4] = {};
        #pragma unroll 8
        for (int d = 0; d < 64; d++) {
            float4 a  = *(const float4*)&qs[d * 68 + 4 * ty];
            float4 bf = *(const float4*)&ks[d * 68 + 4 * tx];
            float av[4] = {a.x, a.y, a.z, a.w};
            float bv[4] = {bf.x, bf.y, bf.z, bf.w};
            #pragma unroll
            for (int i = 0; i < 4; i++)
                #pragma unroll
                for (int j = 0; j < 4; j++)
                    s[i][j] += av[i] * bv[j];
        }

        // scale + mask, write to ps
        #pragma unroll
        for (int i = 0; i < 4; i++) {
            int qg = q0 + 4 * ty + i;
            int4 mv = *reinterpret_cast<const int4*>(&mrow[(size_t)qg * SS + k0 + 4 * tx]);
            float* pr = &ps[(4 * ty + i) * 68 + 4 * tx];
            pr[0] = mv.x ? -1e9f : s[i][0] * 0.125f;
            pr[1] = mv.y ? -1e9f : s[i][1] * 0.125f;
            pr[2] = mv.z ? -1e9f : s[i][2] * 0.125f;
            pr[3] = mv.w ? -1e9f : s[i][3] * 0.125f;
        }
        __syncthreads();

        // online softmax: 4 threads per row (quad = adjacent lanes)
        {
            int r = tid >> 2, g = tid & 3;
            float* prow = ps + r * 68 + g * 16;
            float mx = -INFINITY;
            #pragma unroll
            for (int c = 0; c < 16; c++) mx = fmaxf(mx, prow[c]);
            mx = fmaxf(mx, __shfl_xor_sync(0xffffffffu, mx, 1));
            mx = fmaxf(mx, __shfl_xor_sync(0xffffffffu, mx, 2));
            float mnew = fmaxf(rowm[r], mx);
            float sum = 0.0f;
            #pragma unroll
            for (int c = 0; c < 16; c++) {
                float e = __expf(prow[c] - mnew);
                prow[c] = e;
                sum += e;
            }
            sum += __shfl_xor_sync(0xffffffffu, sum, 1);
            sum += __shfl_xor_sync(0xffffffffu, sum, 2);
            if (g == 0) {
                float al = __expf(rowm[r] - mnew);
                rowa[r] = al;
                rowl[r] = rowl[r] * al + sum;
                rowm[r] = mnew;
            }
        }
        __syncthreads();

        // O = O*alpha + P @ V
        float al[4];
        #pragma unroll
        for (int i = 0; i < 4; i++) al[i] = rowa[4 * ty + i];
        #pragma unroll
        for (int i = 0; i < 4; i++)
            #pragma unroll
            for (int j = 0; j < 4; j++)
                o[i][j] *= al[i];

        #pragma unroll 8
        for (int n = 0; n < 64; n++) {
            float4 bf = *(const float4*)&vs[n * 68 + 4 * tx];
            float bv[4] = {bf.x, bf.y, bf.z, bf.w};
            float av[4];
            #pragma unroll
            for (int i = 0; i < 4; i++) av[i] = ps[(4 * ty + i) * 68 + n];
            #pragma unroll
            for (int i = 0; i < 4; i++)
                #pragma unroll
                for (int j = 0; j < 4; j++)
                    o[i][j] += av[i] * bv[j];
        }
        __syncthreads();
    }

    // normalize and scatter to [B,S,E] with heads interleaved
    #pragma unroll
    for (int i = 0; i < 4; i++) {
        int r = 4 * ty + i;
        float inv = 1.0f / rowl[r];
        int sg = q0 + r;
        float4 v = make_float4(o[i][0] * inv, o[i][1] * inv, o[i][2] * inv, o[i][3] * inv);
        *(float4*)&g_attn[((size_t)(b * SS + sg)) * EE + h * DD + 4 * tx] = v;
    }
}

// ---------------------------------------------------------------------------
extern "C" void kernel_launch(void* const* d_in, const int* in_sizes, int n_in,
                              void* d_out, int out_size)
{
    (void)in_sizes; (void)n_in; (void)out_size;
    const float* Q    = (const float*)d_in[0];
    const float* K    = (const float*)d_in[1];
    const float* V    = (const float*)d_in[2];
    const int*   mask = (const int*)  d_in[3];
    const float* WQ   = (const float*)d_in[4];
    const float* WK   = (const float*)d_in[5];
    const float* WV   = (const float*)d_in[6];
    const float* WO   = (const float*)d_in[7];
    float* out = (float*)d_out;

    float *qh, *kh, *vh, *attn;
    cudaGetSymbolAddress((void**)&qh,   g_qh);
    cudaGetSymbolAddress((void**)&kh,   g_kh);
    cudaGetSymbolAddress((void**)&vh,   g_vh);
    cudaGetSymbolAddress((void**)&attn, g_attn);

    const int FLASH_SMEM = (4 * 64 * 68 + 3 * 64) * (int)sizeof(float);  // 70400 B
    cudaFuncSetAttribute(flash_kernel, cudaFuncAttributeMaxDynamicSharedMemorySize, FLASH_SMEM);

    dim3 pg(EE / 64, MTOT / 64);   // (16, 64)
    proj_kernel<<<pg, 256>>>(Q, WQ, qh, 1);
    proj_kernel<<<pg, 256>>>(K, WK, kh, 1);
    proj_kernel<<<pg, 256>>>(V, WV, vh, 1);

    flash_kernel<<<dim3(SS / 64, BB * HH), 256, FLASH_SMEM>>>(mask);

    proj_kernel<<<pg, 256>>>(attn, WO, out, 0);
}

// round 2
// speedup vs baseline: 2.5208x; 2.5208x over previous
#include <cuda_runtime.h>
#include <math.h>
#include <stdint.h>

#define BB   2
#define SS   2048
#define EE   1024
#define HH   16
#define DD   64
#define MTOT (BB*SS)   // 4096

// Scratch (__device__ globals; allocation-free rule)
__device__ float g_qh[(size_t)BB*HH*SS*DD];   // [B*H][S][D]
__device__ float g_kh[(size_t)BB*HH*SS*DD];
__device__ float g_vh[(size_t)BB*HH*SS*DD];
__device__ float g_attn[(size_t)MTOT*EE];     // [B*S][E]
__device__ uint32_t g_mbits[(size_t)BB*SS*SS/32];  // packed mask bits

// ---------------------------------------------------------------------------
// helpers
// ---------------------------------------------------------------------------
__device__ __forceinline__ uint32_t f2tf(float x) {
    uint32_t r;
    asm("cvt.rna.tf32.f32 %0, %1;" : "=r"(r) : "f"(x));
    return r;
}

__device__ __forceinline__ void mma8(float c[4], const uint32_t a[4],
                                     uint32_t b0, uint32_t b1) {
    asm volatile(
        "mma.sync.aligned.m16n8k8.row.col.f32.tf32.tf32.f32 "
        "{%0,%1,%2,%3}, {%4,%5,%6,%7}, {%8,%9}, {%0,%1,%2,%3};"
        : "+f"(c[0]), "+f"(c[1]), "+f"(c[2]), "+f"(c[3])
        : "r"(a[0]), "r"(a[1]), "r"(a[2]), "r"(a[3]), "r"(b0), "r"(b1));
}

// ---------------------------------------------------------------------------
// mask pack: int32 (nonzero = masked) -> bit per position
// ---------------------------------------------------------------------------
__global__ void pack_mask_kernel(const int* __restrict__ mask,
                                 uint32_t* __restrict__ bits) {
    int idx = blockIdx.x * 256 + threadIdx.x;
    unsigned b = __ballot_sync(0xffffffffu, mask[idx] != 0);
    if ((threadIdx.x & 31) == 0) bits[idx >> 5] = b;
}

// ---------------------------------------------------------------------------
// tf32 tensor-core GEMM: C[M,N] = A[M,K] * W[N,K]^T   (M=4096, N=K=1024)
// 128x128 block tile, BK=32, 256 threads (8 warps, 4m x 2n), warp = 32m x 64n
// mode 0: flat C[m*N+n].  mode 1: head-major scatter [((b*H+h)*S+s)*D+d]
// ---------------------------------------------------------------------------
#define PSTR 36   // 32 + 4 pad (uints)

__global__ void __launch_bounds__(256)
proj_tc_kernel(const float* __restrict__ A, const float* __restrict__ W,
               float* __restrict__ C, int mode)
{
    __shared__ uint32_t As[128 * PSTR];
    __shared__ uint32_t Ws[128 * PSTR];

    const int tid  = threadIdx.x;
    const int lane = tid & 31;
    const int wid  = tid >> 5;
    const int wm   = wid & 3;      // 4 m-warps
    const int wn   = wid >> 2;     // 2 n-warps
    const int gid  = lane >> 2;
    const int tig  = lane & 3;
    const int m0   = blockIdx.y * 128;
    const int n0   = blockIdx.x * 128;

    float acc[2][8][4] = {};

    for (int k0 = 0; k0 < EE; k0 += 32) {
        // global -> smem (tf32-rounded), 1024 float4 per tile
        #pragma unroll
        for (int p = 0; p < 4; p++) {
            int idx = tid + p * 256;
            int r = idx >> 3, c = (idx & 7) * 4;
            float4 va = *(const float4*)&A[(size_t)(m0 + r) * EE + k0 + c];
            uint4 ua = make_uint4(f2tf(va.x), f2tf(va.y), f2tf(va.z), f2tf(va.w));
            *(uint4*)&As[r * PSTR + c] = ua;
            float4 vw = *(const float4*)&W[(size_t)(n0 + r) * EE + k0 + c];
            uint4 uw = make_uint4(f2tf(vw.x), f2tf(vw.y), f2tf(vw.z), f2tf(vw.w));
            *(uint4*)&Ws[r * PSTR + c] = uw;
        }
        __syncthreads();

        #pragma unroll
        for (int kk = 0; kk < 4; kk++) {
            int kb = kk * 8;
            uint32_t af[2][4];
            #pragma unroll
            for (int i = 0; i < 2; i++) {
                int mr = wm * 32 + i * 16 + gid;
                af[i][0] = As[mr * PSTR + kb + tig];
                af[i][1] = As[(mr + 8) * PSTR + kb + tig];
                af[i][2] = As[mr * PSTR + kb + tig + 4];
                af[i][3] = As[(mr + 8) * PSTR + kb + tig + 4];
            }
            #pragma unroll
            for (int j = 0; j < 8; j++) {
                int nr = wn * 64 + j * 8 + gid;
                uint32_t b0 = Ws[nr * PSTR + kb + tig];
                uint32_t b1 = Ws[nr * PSTR + kb + tig + 4];
                mma8(acc[0][j], af[0], b0, b1);
                mma8(acc[1][j], af[1], b0, b1);
            }
        }
        __syncthreads();
    }

    // epilogue
    #pragma unroll
    for (int i = 0; i < 2; i++) {
        #pragma unroll
        for (int j = 0; j < 8; j++) {
            int m = m0 + wm * 32 + i * 16 + gid;
            int n = n0 + wn * 64 + j * 8 + tig * 2;
            if (mode == 0) {
                *(float2*)&C[(size_t)m * EE + n] =
                    make_float2(acc[i][j][0], acc[i][j][1]);
                *(float2*)&C[(size_t)(m + 8) * EE + n] =
                    make_float2(acc[i][j][2], acc[i][j][3]);
            } else {
                int b = m >> 11, s = m & (SS - 1);
                int h = n >> 6,  d = n & 63;
                *(float2*)&g_attn[0] ;  // (dead, keeps compiler honest about aliasing) 
                float* dst0 = &C[(((size_t)(b * HH + h)) * SS + s) * DD + d];
                *(float2*)dst0 = make_float2(acc[i][j][0], acc[i][j][1]);
                int b2 = (m + 8) >> 11, s2 = (m + 8) & (SS - 1);
                float* dst1 = &C[(((size_t)(b2 * HH + h)) * SS + s2) * DD + d];
                *(float2*)dst1 = make_float2(acc[i][j][2], acc[i][j][3]);
            }
        }
    }
}

// ---------------------------------------------------------------------------
// Flash attention with tf32 MMA.
// Block = (b,h) x 64 q-rows, 128 threads (4 warps, 16 q-rows each).
// kv tiles of 64. Q fragments persistent in registers.
// ---------------------------------------------------------------------------
#define FSTR 68   // 64 + 4 pad

__global__ void __launch_bounds__(128)
flash_tc_kernel(const uint32_t* __restrict__ mbits)
{
    extern __shared__ uint32_t fsm[];
    uint32_t* ks = fsm;                 // [64][68] K row-major (tf32)
    uint32_t* vs = fsm + 64 * FSTR;     // [64][68] V row-major (tf32)
    uint32_t* ps = fsm + 2 * 64 * FSTR; // [64][68] P staging (tf32)

    const int tid  = threadIdx.x;
    const int lane = tid & 31;
    const int w    = tid >> 5;
    const int gid  = lane >> 2;
    const int tig  = lane & 3;
    const int bh   = blockIdx.y;
    const int b    = bh >> 4, h = bh & 15;
    const int q0   = blockIdx.x * 64;
    const int r0   = w * 16 + gid;     // this lane's two q-rows within tile
    const int r1   = r0 + 8;

    const float* qp = g_qh + (size_t)bh * SS * DD;
    const float* kp = g_kh + (size_t)bh * SS * DD;
    const float* vp = g_vh + (size_t)bh * SS * DD;
    const uint32_t* mrow0 = mbits + ((size_t)(b * SS + q0 + r0) << 6); // SS/32=64 words/row
    const uint32_t* mrow1 = mbits + ((size_t)(b * SS + q0 + r1) << 6);

    // persistent Q fragments (8 k-steps x 4 regs)
    uint32_t qa[8][4];
    #pragma unroll
    for (int t = 0; t < 8; t++) {
        qa[t][0] = f2tf(qp[(size_t)(q0 + r0) * DD + t * 8 + tig]);
        qa[t][1] = f2tf(qp[(size_t)(q0 + r1) * DD + t * 8 + tig]);
        qa[t][2] = f2tf(qp[(size_t)(q0 + r0) * DD + t * 8 + tig + 4]);
        qa[t][3] = f2tf(qp[(size_t)(q0 + r1) * DD + t * 8 + tig + 4]);
    }

    float o[8][4] = {};
    float mprev0 = -INFINITY, mprev1 = -INFINITY;
    float l0 = 0.0f, l1 = 0.0f;

    for (int kv0 = 0; kv0 < SS; kv0 += 64) {
        __syncthreads();  // previous iter's smem reads complete
        // load K,V tiles (tf32-rounded): 1024 float4 across 128 threads
        #pragma unroll
        for (int p = 0; p < 8; p++) {
            int idx = tid + p * 128;
            int r = idx >> 4, c = (idx & 15) * 4;
            float4 kv4 = *(const float4*)&kp[(size_t)(kv0 + r) * DD + c];
            *(uint4*)&ks[r * FSTR + c] =
                make_uint4(f2tf(kv4.x), f2tf(kv4.y), f2tf(kv4.z), f2tf(kv4.w));
            float4 vv4 = *(const float4*)&vp[(size_t)(kv0 + r) * DD + c];
            *(uint4*)&vs[r * FSTR + c] =
                make_uint4(f2tf(vv4.x), f2tf(vv4.y), f2tf(vv4.z), f2tf(vv4.w));
        }
        __syncthreads();

        // S = Q @ K^T  (m16 x n64 x k64 per warp)
        float s[8][4] = {};
        #pragma unroll
        for (int t = 0; t < 8; t++) {
            int kb = t * 8;
            #pragma unroll
            for (int j = 0; j < 8; j++) {
                uint32_t b0 = ks[(j * 8 + gid) * FSTR + kb + tig];
                uint32_t b1 = ks[(j * 8 + gid) * FSTR + kb + tig + 4];
                mma8(s[j], qa[t], b0, b1);
            }
        }

        // scale + mask
        uint32_t mw00 = mrow0[kv0 >> 5], mw01 = mrow0[(kv0 >> 5) + 1];
        uint32_t mw10 = mrow1[kv0 >> 5], mw11 = mrow1[(kv0 >> 5) + 1];
        #pragma unroll
        for (int j = 0; j < 8; j++) {
            int c0 = j * 8 + tig * 2;
            uint32_t wr0 = (j < 4) ? mw00 : mw01;
            uint32_t wr1 = (j < 4) ? mw10 : mw11;
            s[j][0] = ((wr0 >> (c0 & 31)) & 1)        ? -1e9f : s[j][0] * 0.125f;
            s[j][1] = ((wr0 >> ((c0 + 1) & 31)) & 1)  ? -1e9f : s[j][1] * 0.125f;
            s[j][2] = ((wr1 >> (c0 & 31)) & 1)        ? -1e9f : s[j][2] * 0.125f;
            s[j][3] = ((wr1 >> ((c0 + 1) & 31)) & 1)  ? -1e9f : s[j][3] * 0.125f;
        }

        // online softmax (rows spread over 4 lanes of a quad)
        float mx0 = -INFINITY, mx1 = -INFINITY;
        #pragma unroll
        for (int j = 0; j < 8; j++) {
            mx0 = fmaxf(mx0, fmaxf(s[j][0], s[j][1]));
            mx1 = fmaxf(mx1, fmaxf(s[j][2], s[j][3]));
        }
        mx0 = fmaxf(mx0, __shfl_xor_sync(0xffffffffu, mx0, 1));
        mx0 = fmaxf(mx0, __shfl_xor_sync(0xffffffffu, mx0, 2));
        mx1 = fmaxf(mx1, __shfl_xor_sync(0xffffffffu, mx1, 1));
        mx1 = fmaxf(mx1, __shfl_xor_sync(0xffffffffu, mx1, 2));

        float mn0 = fmaxf(mprev0, mx0), mn1 = fmaxf(mprev1, mx1);
        float al0 = __expf(mprev0 - mn0), al1 = __expf(mprev1 - mn1);
        mprev0 = mn0; mprev1 = mn1;

        float sum0 = 0.0f, sum1 = 0.0f;
        #pragma unroll
        for (int j = 0; j < 8; j++) {
            s[j][0] = __expf(s[j][0] - mn0); sum0 += s[j][0];
            s[j][1] = __expf(s[j][1] - mn0); sum0 += s[j][1];
            s[j][2] = __expf(s[j][2] - mn1); sum1 += s[j][2];
            s[j][3] = __expf(s[j][3] - mn1); sum1 += s[j][3];
        }
        sum0 += __shfl_xor_sync(0xffffffffu, sum0, 1);
        sum0 += __shfl_xor_sync(0xffffffffu, sum0, 2);
        sum1 += __shfl_xor_sync(0xffffffffu, sum1, 1);
        sum1 += __shfl_xor_sync(0xffffffffu, sum1, 2);
        l0 = l0 * al0 + sum0;
        l1 = l1 * al1 + sum1;

        #pragma unroll
        for (int j = 0; j < 8; j++) {
            o[j][0] *= al0; o[j][1] *= al0;
            o[j][2] *= al1; o[j][3] *= al1;
        }

        // stage P (tf32) in per-warp smem region
        #pragma unroll
        for (int j = 0; j < 8; j++) {
            int c0 = j * 8 + tig * 2;
            ps[(w * 16 + gid) * FSTR + c0]     = f2tf(s[j][0]);
            ps[(w * 16 + gid) * FSTR + c0 + 1] = f2tf(s[j][1]);
            ps[(w * 16 + gid + 8) * FSTR + c0]     = f2tf(s[j][2]);
            ps[(w * 16 + gid + 8) * FSTR + c0 + 1] = f2tf(s[j][3]);
        }
        __syncwarp();

        // O += P @ V  (m16 x n64 x k64)
        #pragma unroll
        for (int t = 0; t < 8; t++) {
            int kb = t * 8;
            uint32_t pa[4];
            pa[0] = ps[(w * 16 + gid) * FSTR + kb + tig];
            pa[1] = ps[(w * 16 + gid + 8) * FSTR + kb + tig];
            pa[2] = ps[(w * 16 + gid) * FSTR + kb + tig + 4];
            pa[3] = ps[(w * 16 + gid + 8) * FSTR + kb + tig + 4];
            #pragma unroll
            for (int j = 0; j < 8; j++) {
                uint32_t b0 = vs[(kb + tig) * FSTR + j * 8 + gid];
                uint32_t b1 = vs[(kb + tig + 4) * FSTR + j * 8 + gid];
                mma8(o[j], pa, b0, b1);
            }
        }
    }

    // normalize + scatter into [B,S,E]
    float i0 = 1.0f / l0, i1 = 1.0f / l1;
    #pragma unroll
    for (int j = 0; j < 8; j++) {
        int c0 = h * 64 + j * 8 + tig * 2;
        *(float2*)&g_attn[((size_t)(b * SS + q0 + r0)) * EE + c0] =
            make_float2(o[j][0] * i0, o[j][1] * i0);
        *(float2*)&g_attn[((size_t)(b * SS + q0 + r1)) * EE + c0] =
            make_float2(o[j][2] * i1, o[j][3] * i1);
    }
}

// ---------------------------------------------------------------------------
extern "C" void kernel_launch(void* const* d_in, const int* in_sizes, int n_in,
                              void* d_out, int out_size)
{
    (void)in_sizes; (void)n_in; (void)out_size;
    const float* Q    = (const float*)d_in[0];
    const float* K    = (const float*)d_in[1];
    const float* V    = (const float*)d_in[2];
    const int*   mask = (const int*)  d_in[3];
    const float* WQ   = (const float*)d_in[4];
    const float* WK   = (const float*)d_in[5];
    const float* WV   = (const float*)d_in[6];
    const float* WO   = (const float*)d_in[7];
    float* out = (float*)d_out;

    float *qh, *kh, *vh, *attn;
    uint32_t* mbits;
    cudaGetSymbolAddress((void**)&qh,    g_qh);
    cudaGetSymbolAddress((void**)&kh,    g_kh);
    cudaGetSymbolAddress((void**)&vh,    g_vh);
    cudaGetSymbolAddress((void**)&attn,  g_attn);
    cudaGetSymbolAddress((void**)&mbits, g_mbits);

    const int FLASH_SMEM = 3 * 64 * FSTR * (int)sizeof(uint32_t);  // 52224 B
    cudaFuncSetAttribute(flash_tc_kernel,
                         cudaFuncAttributeMaxDynamicSharedMemorySize, FLASH_SMEM);

    pack_mask_kernel<<<BB * SS * SS / (32 * 256) * 32, 256>>>(mask, mbits);

    dim3 pg(EE / 128, MTOT / 128);   // (8, 32)
    proj_tc_kernel<<<pg, 256>>>(Q, WQ, qh, 1);
    proj_tc_kernel<<<pg, 256>>>(K, WK, kh, 1);
    proj_tc_kernel<<<pg, 256>>>(V, WV, vh, 1);

    flash_tc_kernel<<<dim3(SS / 64, BB * HH), 128, FLASH_SMEM>>>(mbits);

    proj_tc_kernel<<<pg, 256>>>(attn, WO, out, 0);
}

// round 3
// speedup vs baseline: 2.9079x; 1.1536x over previous
#include <cuda_runtime.h>
#include <math.h>
#include <stdint.h>

#define BB   2
#define SS   2048
#define EE   1024
#define HH   16
#define DD   64
#define MTOT (BB*SS)   // 4096

// Scratch (__device__ globals; allocation-free rule)
__device__ float g_qh[(size_t)BB*HH*SS*DD];
__device__ float g_kh[(size_t)BB*HH*SS*DD];
__device__ float g_vh[(size_t)BB*HH*SS*DD];
__device__ float g_attn[(size_t)MTOT*EE];
__device__ uint32_t g_mbits[(size_t)BB*SS*SS/32];

// ---------------------------------------------------------------------------
__device__ __forceinline__ uint32_t f2tf(float x) {
    uint32_t r;
    asm("cvt.rna.tf32.f32 %0, %1;" : "=r"(r) : "f"(x));
    return r;
}

__device__ __forceinline__ void mma8(float c[4], const uint32_t a[4],
                                     uint32_t b0, uint32_t b1) {
    asm volatile(
        "mma.sync.aligned.m16n8k8.row.col.f32.tf32.tf32.f32 "
        "{%0,%1,%2,%3}, {%4,%5,%6,%7}, {%8,%9}, {%0,%1,%2,%3};"
        : "+f"(c[0]), "+f"(c[1]), "+f"(c[2]), "+f"(c[3])
        : "r"(a[0]), "r"(a[1]), "r"(a[2]), "r"(a[3]), "r"(b0), "r"(b1));
}

__device__ __forceinline__ void cpa16(void* sm, const void* gm) {
    uint32_t s = (uint32_t)__cvta_generic_to_shared(sm);
    asm volatile("cp.async.ca.shared.global [%0], [%1], 16;" :: "r"(s), "l"(gm));
}
__device__ __forceinline__ void cp_commit() {
    asm volatile("cp.async.commit_group;");
}
template<int N> __device__ __forceinline__ void cp_wait() {
    asm volatile("cp.async.wait_group %0;" :: "n"(N));
}

// ---------------------------------------------------------------------------
__global__ void pack_mask_kernel(const int* __restrict__ mask,
                                 uint32_t* __restrict__ bits) {
    int idx = blockIdx.x * 256 + threadIdx.x;
    unsigned b = __ballot_sync(0xffffffffu, mask[idx] != 0);
    if ((threadIdx.x & 31) == 0) bits[idx >> 5] = b;
}

// ---------------------------------------------------------------------------
// tf32 GEMM: C[M,N] = A[M,K] * W[N,K]^T   (M=4096, N=K=1024)
// Block 128x128, 4 warps (2m x 2n), warp 64x64. BK=32, 3-stage cp.async.
// Raw f32 in smem; cvt.rna at fragment load.
// ---------------------------------------------------------------------------
#define PST    36     // floats per smem row (32 + 4 pad, 16B-aligned stride)
#define STAGES 3

__global__ void __launch_bounds__(128)
proj_tc_kernel(const float* __restrict__ A, const float* __restrict__ W,
               float* __restrict__ C, int mode)
{
    extern __shared__ float psm[];
    float* AS = psm;                        // [3][128][36]
    float* WS = psm + STAGES * 128 * PST;   // [3][128][36]

    const int tid  = threadIdx.x;
    const int lane = tid & 31;
    const int wid  = tid >> 5;
    const int wm   = wid & 1;
    const int wn   = wid >> 1;
    const int gid  = lane >> 2;
    const int tig  = lane & 3;
    const int m0   = blockIdx.y * 128;
    const int n0   = blockIdx.x * 128;

    auto load_stage = [&](int st, int k0) {
        float* as = AS + st * 128 * PST;
        float* ws = WS + st * 128 * PST;
        #pragma unroll
        for (int p = 0; p < 8; p++) {
            int idx = tid + p * 128;
            int r = idx >> 3, c = (idx & 7) * 4;
            cpa16(&as[r * PST + c], &A[(size_t)(m0 + r) * EE + k0 + c]);
            cpa16(&ws[r * PST + c], &W[(size_t)(n0 + r) * EE + k0 + c]);
        }
    };

    float acc[4][8][4] = {};

    load_stage(0, 0);  cp_commit();
    load_stage(1, 32); cp_commit();

    const int KT = EE / 32;  // 32
    for (int kt = 0; kt < KT; kt++) {
        cp_wait<1>();
        __syncthreads();
        int st = kt % STAGES;
        if (kt + 2 < KT) load_stage((kt + 2) % STAGES, (kt + 2) * 32);
        cp_commit();

        const float* as = AS + st * 128 * PST;
        const float* ws = WS + st * 128 * PST;
        #pragma unroll
        for (int kk = 0; kk < 4; kk++) {
            int kb = kk * 8;
            uint32_t a[4][4];
            #pragma unroll
            for (int i = 0; i < 4; i++) {
                int r = wm * 64 + i * 16 + gid;
                a[i][0] = f2tf(as[r * PST + kb + tig]);
                a[i][1] = f2tf(as[(r + 8) * PST + kb + tig]);
                a[i][2] = f2tf(as[r * PST + kb + tig + 4]);
                a[i][3] = f2tf(as[(r + 8) * PST + kb + tig + 4]);
            }
            #pragma unroll
            for (int j = 0; j < 8; j++) {
                int nr = wn * 64 + j * 8 + gid;
                uint32_t b0 = f2tf(ws[nr * PST + kb + tig]);
                uint32_t b1 = f2tf(ws[nr * PST + kb + tig + 4]);
                #pragma unroll
                for (int i = 0; i < 4; i++)
                    mma8(acc[i][j], a[i], b0, b1);
            }
        }
    }

    // epilogue
    #pragma unroll
    for (int i = 0; i < 4; i++) {
        #pragma unroll
        for (int j = 0; j < 8; j++) {
            int m = m0 + wm * 64 + i * 16 + gid;
            int n = n0 + wn * 64 + j * 8 + tig * 2;
            if (mode == 0) {
                *(float2*)&C[(size_t)m * EE + n] =
                    make_float2(acc[i][j][0], acc[i][j][1]);
                *(float2*)&C[(size_t)(m + 8) * EE + n] =
                    make_float2(acc[i][j][2], acc[i][j][3]);
            } else {
                int h = n >> 6, d = n & 63;
                int b1_ = m >> 11, s1 = m & (SS - 1);
                *(float2*)&C[(((size_t)(b1_ * HH + h)) * SS + s1) * DD + d] =
                    make_float2(acc[i][j][0], acc[i][j][1]);
                int b2 = (m + 8) >> 11, s2 = (m + 8) & (SS - 1);
                *(float2*)&C[(((size_t)(b2 * HH + h)) * SS + s2) * DD + d] =
                    make_float2(acc[i][j][2], acc[i][j][3]);
            }
        }
    }
}

// ---------------------------------------------------------------------------
// Flash attention, tf32 MMA. Block = (b,h) x 128 q-rows, 4 warps.
// Warp tile 32 q-rows x 64 kv. Q fragments persistent in regs.
// qs smem doubles as P staging after the Q prologue (per-warp row ranges).
// ---------------------------------------------------------------------------
#define FST 68   // 64 + 4 pad

__global__ void __launch_bounds__(128)
flash_tc_kernel(const uint32_t* __restrict__ mbits)
{
    extern __shared__ uint32_t fsm[];
    uint32_t* qs = fsm;              // [128][68]: tf32 Q, then P staging
    uint32_t* ks = fsm + 128 * FST;  // [64][68]
    uint32_t* vs = ks + 64 * FST;    // [64][68]

    const int tid  = threadIdx.x;
    const int lane = tid & 31;
    const int w    = tid >> 5;
    const int gid  = lane >> 2;
    const int tig  = lane & 3;
    const int bh   = blockIdx.y;
    const int b    = bh >> 4, h = bh & 15;
    const int q0   = blockIdx.x * 128;

    const float* qp = g_qh + (size_t)bh * SS * DD;
    const float* kp = g_kh + (size_t)bh * SS * DD;
    const float* vp = g_vh + (size_t)bh * SS * DD;

    const uint32_t* mrow[2][2];
    #pragma unroll
    for (int u = 0; u < 2; u++)
        #pragma unroll
        for (int v = 0; v < 2; v++)
            mrow[u][v] = mbits +
                ((size_t)(b * SS + q0 + w * 32 + u * 16 + gid + v * 8) << 6);

    // stage Q (coalesced, tf32-rounded)
    #pragma unroll
    for (int p = 0; p < 16; p++) {
        int idx = tid + p * 128;
        int r = idx >> 4, c = (idx & 15) * 4;
        float4 v4 = *(const float4*)&qp[(size_t)(q0 + r) * DD + c];
        *(uint4*)&qs[r * FST + c] =
            make_uint4(f2tf(v4.x), f2tf(v4.y), f2tf(v4.z), f2tf(v4.w));
    }
    __syncthreads();

    // persistent Q fragments (own 32 rows only)
    uint32_t qa[2][8][4];
    #pragma unroll
    for (int u = 0; u < 2; u++) {
        int r = w * 32 + u * 16 + gid;
        #pragma unroll
        for (int t = 0; t < 8; t++) {
            qa[u][t][0] = qs[r * FST + t * 8 + tig];
            qa[u][t][1] = qs[(r + 8) * FST + t * 8 + tig];
            qa[u][t][2] = qs[r * FST + t * 8 + tig + 4];
            qa[u][t][3] = qs[(r + 8) * FST + t * 8 + tig + 4];
        }
    }

    float o[2][8][4] = {};
    float mpr[2][2] = {{-INFINITY, -INFINITY}, {-INFINITY, -INFINITY}};
    float l[2][2] = {};

    for (int kv0 = 0; kv0 < SS; kv0 += 64) {
        __syncthreads();   // prior QK/PV smem reads complete before overwrite
        #pragma unroll
        for (int p = 0; p < 8; p++) {
            int idx = tid + p * 128;
            int r = idx >> 4, c = (idx & 15) * 4;
            float4 k4 = *(const float4*)&kp[(size_t)(kv0 + r) * DD + c];
            *(uint4*)&ks[r * FST + c] =
                make_uint4(f2tf(k4.x), f2tf(k4.y), f2tf(k4.z), f2tf(k4.w));
            float4 v4 = *(const float4*)&vp[(size_t)(kv0 + r) * DD + c];
            *(uint4*)&vs[r * FST + c] =
                make_uint4(f2tf(v4.x), f2tf(v4.y), f2tf(v4.z), f2tf(v4.w));
        }
        __syncthreads();

        // S = Q @ K^T
        float s[2][8][4] = {};
        #pragma unroll
        for (int t = 0; t < 8; t++) {
            #pragma unroll
            for (int j = 0; j < 8; j++) {
                uint32_t b0 = ks[(j * 8 + gid) * FST + t * 8 + tig];
                uint32_t b1 = ks[(j * 8 + gid) * FST + t * 8 + tig + 4];
                mma8(s[0][j], qa[0][t], b0, b1);
                mma8(s[1][j], qa[1][t], b0, b1);
            }
        }

        // scale + mask
        int wq = kv0 >> 5;
        #pragma unroll
        for (int u = 0; u < 2; u++) {
            uint32_t wa0 = mrow[u][0][wq], wa1 = mrow[u][0][wq + 1];
            uint32_t wb0 = mrow[u][1][wq], wb1 = mrow[u][1][wq + 1];
            #pragma unroll
            for (int j = 0; j < 8; j++) {
                int c0 = j * 8 + tig * 2;
                uint32_t wra = (j < 4) ? wa0 : wa1;
                uint32_t wrb = (j < 4) ? wb0 : wb1;
                s[u][j][0] = ((wra >> (c0 & 31)) & 1)       ? -1e9f : s[u][j][0] * 0.125f;
                s[u][j][1] = ((wra >> ((c0 + 1) & 31)) & 1) ? -1e9f : s[u][j][1] * 0.125f;
                s[u][j][2] = ((wrb >> (c0 & 31)) & 1)       ? -1e9f : s[u][j][2] * 0.125f;
                s[u][j][3] = ((wrb >> ((c0 + 1) & 31)) & 1) ? -1e9f : s[u][j][3] * 0.125f;
            }
        }

        // online softmax
        #pragma unroll
        for (int u = 0; u < 2; u++) {
            float mx0 = -INFINITY, mx1 = -INFINITY;
            #pragma unroll
            for (int j = 0; j < 8; j++) {
                mx0 = fmaxf(mx0, fmaxf(s[u][j][0], s[u][j][1]));
                mx1 = fmaxf(mx1, fmaxf(s[u][j][2], s[u][j][3]));
            }
            mx0 = fmaxf(mx0, __shfl_xor_sync(0xffffffffu, mx0, 1));
            mx0 = fmaxf(mx0, __shfl_xor_sync(0xffffffffu, mx0, 2));
            mx1 = fmaxf(mx1, __shfl_xor_sync(0xffffffffu, mx1, 1));
            mx1 = fmaxf(mx1, __shfl_xor_sync(0xffffffffu, mx1, 2));
            float mn0 = fmaxf(mpr[u][0], mx0), mn1 = fmaxf(mpr[u][1], mx1);
            float al0 = __expf(mpr[u][0] - mn0), al1 = __expf(mpr[u][1] - mn1);
            mpr[u][0] = mn0; mpr[u][1] = mn1;
            float sum0 = 0.0f, sum1 = 0.0f;
            #pragma unroll
            for (int j = 0; j < 8; j++) {
                s[u][j][0] = __expf(s[u][j][0] - mn0); sum0 += s[u][j][0];
                s[u][j][1] = __expf(s[u][j][1] - mn0); sum0 += s[u][j][1];
                s[u][j][2] = __expf(s[u][j][2] - mn1); sum1 += s[u][j][2];
                s[u][j][3] = __expf(s[u][j][3] - mn1); sum1 += s[u][j][3];
            }
            sum0 += __shfl_xor_sync(0xffffffffu, sum0, 1);
            sum0 += __shfl_xor_sync(0xffffffffu, sum0, 2);
            sum1 += __shfl_xor_sync(0xffffffffu, sum1, 1);
            sum1 += __shfl_xor_sync(0xffffffffu, sum1, 2);
            l[u][0] = l[u][0] * al0 + sum0;
            l[u][1] = l[u][1] * al1 + sum1;
            #pragma unroll
            for (int j = 0; j < 8; j++) {
                o[u][j][0] *= al0; o[u][j][1] *= al0;
                o[u][j][2] *= al1; o[u][j][3] *= al1;
            }
        }

        // stage P (tf32) into own rows of qs
        #pragma unroll
        for (int u = 0; u < 2; u++) {
            int row = w * 32 + u * 16 + gid;
            #pragma unroll
            for (int j = 0; j < 8; j++) {
                int c0 = j * 8 + tig * 2;
                qs[row * FST + c0]           = f2tf(s[u][j][0]);
                qs[row * FST + c0 + 1]       = f2tf(s[u][j][1]);
                qs[(row + 8) * FST + c0]     = f2tf(s[u][j][2]);
                qs[(row + 8) * FST + c0 + 1] = f2tf(s[u][j][3]);
            }
        }
        __syncwarp();

        // O += P @ V
        #pragma unroll
        for (int t = 0; t < 8; t++) {
            uint32_t pa[2][4];
            #pragma unroll
            for (int u = 0; u < 2; u++) {
                int row = w * 32 + u * 16 + gid;
                pa[u][0] = qs[row * FST + t * 8 + tig];
                pa[u][1] = qs[(row + 8) * FST + t * 8 + tig];
                pa[u][2] = qs[row * FST + t * 8 + tig + 4];
                pa[u][3] = qs[(row + 8) * FST + t * 8 + tig + 4];
            }
            #pragma unroll
            for (int j = 0; j < 8; j++) {
                uint32_t b0 = vs[(t * 8 + tig) * FST + j * 8 + gid];
                uint32_t b1 = vs[(t * 8 + tig + 4) * FST + j * 8 + gid];
                mma8(o[0][j], pa[0], b0, b1);
                mma8(o[1][j], pa[1], b0, b1);
            }
        }
    }

    // normalize + scatter to [B,S,E]
    #pragma unroll
    for (int u = 0; u < 2; u++) {
        float i0 = 1.0f / l[u][0], i1 = 1.0f / l[u][1];
        int row = q0 + w * 32 + u * 16 + gid;
        #pragma unroll
        for (int j = 0; j < 8; j++) {
            int c0 = h * 64 + j * 8 + tig * 2;
            *(float2*)&g_attn[((size_t)(b * SS + row)) * EE + c0] =
                make_float2(o[u][j][0] * i0, o[u][j][1] * i0);
            *(float2*)&g_attn[((size_t)(b * SS + row + 8)) * EE + c0] =
                make_float2(o[u][j][2] * i1, o[u][j][3] * i1);
        }
    }
}

// ---------------------------------------------------------------------------
extern "C" void kernel_launch(void* const* d_in, const int* in_sizes, int n_in,
                              void* d_out, int out_size)
{
    (void)in_sizes; (void)n_in; (void)out_size;
    const float* Q    = (const float*)d_in[0];
    const float* K    = (const float*)d_in[1];
    const float* V    = (const float*)d_in[2];
    const int*   mask = (const int*)  d_in[3];
    const float* WQ   = (const float*)d_in[4];
    const float* WK   = (const float*)d_in[5];
    const float* WV   = (const float*)d_in[6];
    const float* WO   = (const float*)d_in[7];
    float* out = (float*)d_out;

    float *qh, *kh, *vh, *attn;
    uint32_t* mbits;
    cudaGetSymbolAddress((void**)&qh,    g_qh);
    cudaGetSymbolAddress((void**)&kh,    g_kh);
    cudaGetSymbolAddress((void**)&vh,    g_vh);
    cudaGetSymbolAddress((void**)&attn,  g_attn);
    cudaGetSymbolAddress((void**)&mbits, g_mbits);

    const int PROJ_SMEM  = 2 * STAGES * 128 * PST * (int)sizeof(float);     // 110592
    const int FLASH_SMEM = (128 + 64 + 64) * FST * (int)sizeof(uint32_t);   // 69632
    cudaFuncSetAttribute(proj_tc_kernel,
                         cudaFuncAttributeMaxDynamicSharedMemorySize, PROJ_SMEM);
    cudaFuncSetAttribute(flash_tc_kernel,
                         cudaFuncAttributeMaxDynamicSharedMemorySize, FLASH_SMEM);

    pack_mask_kernel<<<BB * SS * SS / 256, 256>>>(mask, mbits);

    dim3 pg(EE / 128, MTOT / 128);   // (8, 32)
    proj_tc_kernel<<<pg, 128, PROJ_SMEM>>>(Q, WQ, qh, 1);
    proj_tc_kernel<<<pg, 128, PROJ_SMEM>>>(K, WK, kh, 1);
    proj_tc_kernel<<<pg, 128, PROJ_SMEM>>>(V, WV, vh, 1);

    flash_tc_kernel<<<dim3(SS / 128, BB * HH), 128, FLASH_SMEM>>>(mbits);

    proj_tc_kernel<<<pg, 128, PROJ_SMEM>>>(attn, WO, out, 0);
}